// round 13
// baseline (speedup 1.0000x reference)
#include <cuda_runtime.h>
#include <cuda_bf16.h>
#include <math.h>
#include <stdint.h>

#define BB 4
#define TT_SEQ 4096
#define DD 1024
#define HD 64
#define NTOK (BB*TT_SEQ)

#define QT 128
#define CK 512
#define TILES (TT_SEQ/QT)      // 32
#define NCH_MAX (TT_SEQ/CK)    // 8

// W in bf16 hi/lo, rows 0-63=Wq(*0.125), 64-127=Wk, 128-191=Wv
__device__ __nv_bfloat16 g_Whi[3*HD*DD];
__device__ __nv_bfloat16 g_Wlo[3*HD*DD];

// Q/K/V stored ONLY as packed bf16 hi/lo. Q pre-scaled by hd^-0.5.
__device__ __nv_bfloat16 g_Qhi[NTOK*HD];
__device__ __nv_bfloat16 g_Qlo[NTOK*HD];
__device__ __nv_bfloat16 g_Khi[NTOK*HD];
__device__ __nv_bfloat16 g_Klo[NTOK*HD];
__device__ __nv_bfloat16 g_Vhi[NTOK*HD];
__device__ __nv_bfloat16 g_Vlo[NTOK*HD];

// Split-K partials
__device__ float g_pacc[BB*TILES*NCH_MAX*QT*HD];
__device__ float g_pm  [BB*TILES*NCH_MAX*QT];
__device__ float g_pl  [BB*TILES*NCH_MAX*QT];

__device__ __forceinline__ uint32_t pack_bf16(float a, float b) {
    __nv_bfloat162 t = __floats2bfloat162_rn(a, b);
    return *reinterpret_cast<uint32_t*>(&t);
}

__device__ __forceinline__ void split2(float a, float b, uint32_t& hi, uint32_t& lo) {
    __nv_bfloat162 h = __floats2bfloat162_rn(a, b);
    hi = *reinterpret_cast<uint32_t*>(&h);
    lo = pack_bf16(a - __bfloat162float(h.x), b - __bfloat162float(h.y));
}

__device__ __forceinline__ void mma16816(float* d, const uint32_t* a, const uint32_t* b) {
    asm volatile(
        "mma.sync.aligned.m16n8k16.row.col.f32.bf16.bf16.f32 "
        "{%0,%1,%2,%3}, {%4,%5,%6,%7}, {%8,%9}, {%0,%1,%2,%3};"
        : "+f"(d[0]), "+f"(d[1]), "+f"(d[2]), "+f"(d[3])
        : "r"(a[0]), "r"(a[1]), "r"(a[2]), "r"(a[3]),
          "r"(b[0]), "r"(b[1]));
}

__device__ __forceinline__ void ldsm4(uint32_t* d, uint32_t addr) {
    asm volatile("ldmatrix.sync.aligned.m8n8.x4.shared.b16 {%0,%1,%2,%3}, [%4];"
        : "=r"(d[0]), "=r"(d[1]), "=r"(d[2]), "=r"(d[3]) : "r"(addr));
}
__device__ __forceinline__ void ldsm4t(uint32_t* d, uint32_t addr) {
    asm volatile("ldmatrix.sync.aligned.m8n8.x4.trans.shared.b16 {%0,%1,%2,%3}, [%4];"
        : "=r"(d[0]), "=r"(d[1]), "=r"(d[2]), "=r"(d[3]) : "r"(addr));
}

#define CP_ASYNC16(saddr, gptr) \
    asm volatile("cp.async.cg.shared.global [%0], [%1], 16;" :: "r"(saddr), "l"(gptr) : "memory")
#define CP_COMMIT() asm volatile("cp.async.commit_group;" ::: "memory")
#define CP_WAIT0()  asm volatile("cp.async.wait_group 0;" ::: "memory")
#define CP_WAIT1()  asm volatile("cp.async.wait_group 1;" ::: "memory")

// ---------------------------------------------------------------------------
// Kernel 0: convert W (fp32 -> bf16 hi/lo), fold 1/8 into Wq.
// ---------------------------------------------------------------------------
__global__ __launch_bounds__(256) void convert_w(
    const float* __restrict__ Wq,
    const float* __restrict__ Wk,
    const float* __restrict__ Wv)
{
    const int idx = blockIdx.x * 256 + threadIdx.x;
    const int e0  = idx * 4;
    const int row = e0 >> 10;
    const int col = e0 & 1023;
    const float* src = (row < 64) ? Wq + (size_t)row * DD
                     : (row < 128) ? Wk + (size_t)(row - 64) * DD
                                   : Wv + (size_t)(row - 128) * DD;
    const float sc = (row < 64) ? 0.125f : 1.0f;
    float4 v = *(const float4*)(src + col);
    v.x *= sc; v.y *= sc; v.z *= sc; v.w *= sc;

    uint2 hi, lo;
    split2(v.x, v.y, hi.x, lo.x);
    split2(v.z, v.w, hi.y, lo.y);

    *(uint2*)(g_Whi + e0) = hi;
    *(uint2*)(g_Wlo + e0) = lo;
}

// ---------------------------------------------------------------------------
// Kernel 1: FUSED QKV projection. One CTA = 64 tokens x all 192 outputs.
// 128 threads (4 warps, 2Mx2N, warp tile 32x96). 3 CTAs/SM, grid=256.
// X loaded fp32 + split once per tile (register-prefetched, single buffer);
// W (preconverted bf16 hi/lo) double-buffered via cp.async.
// ---------------------------------------------------------------------------
#define GM_BM 64
#define GM_BK 32
#define XLD 40
#define WLD 40
#define X_ARR (GM_BM * XLD * 2)        // 5120 B (one of hi/lo)
#define W_ARR (192 * WLD * 2)          // 15360 B
#define WBUF  (2 * W_ARR)              // 30720 B
#define QKV_SMEM (2 * X_ARR + 2 * WBUF)  // 71680 B

__global__ __launch_bounds__(128, 3) void qkv_fused(const float* __restrict__ x)
{
    extern __shared__ char qsm[];
    __nv_bfloat16* xhi = (__nv_bfloat16*)qsm;
    __nv_bfloat16* xlo = (__nv_bfloat16*)(qsm + X_ARR);

    const int m0 = blockIdx.x * GM_BM;

    const int tid  = threadIdx.x;
    const int warp = tid >> 5;
    const int lane = tid & 31;
    const int wm   = (warp & 1) * 32;     // warp M offset
    const int wn   = (warp >> 1) * 96;    // warp N offset (0 or 96)
    const int g    = lane >> 2;
    const int t4   = lane & 3;

    const int la = lane >> 3;
    const int lr = lane & 7;
    const uint32_t a_off = (uint32_t)((((la & 1) * 8 + lr) * XLD + (la >> 1) * 8) * 2);
    const uint32_t b_off = (uint32_t)((((la >> 1) * 8 + lr) * WLD + (la & 1) * 8) * 2);

    const uint32_t sb    = (uint32_t)__cvta_generic_to_shared(qsm);
    const uint32_t xhi_s = sb + (uint32_t)(wm * XLD * 2) + a_off;
    const uint32_t xlo_s = xhi_s + X_ARR;

    float acc[2][12][4];
    #pragma unroll
    for (int mi = 0; mi < 2; mi++)
        #pragma unroll
        for (int ni = 0; ni < 12; ni++)
            #pragma unroll
            for (int e = 0; e < 4; e++) acc[mi][ni][e] = 0.f;

    const int xr = tid >> 1;       // X row this thread stages (0..63)
    const int xp = tid & 1;        // 16-float half

    // W staging: 768 16B-slots per array, 6 per thread
    auto stage_w = [&](uint32_t wbase, int k0) {
        #pragma unroll
        for (int i = 0; i < 6; i++) {
            const int s   = i * 128 + tid;
            const int row = s >> 2;
            const int seg = (s & 3) * 8;
            const size_t gof = (size_t)row * DD + k0 + seg;
            const uint32_t sdst = wbase + (uint32_t)((row * WLD + seg) * 2);
            CP_ASYNC16(sdst,         g_Whi + gof);
            CP_ASYNC16(sdst + W_ARR, g_Wlo + gof);
        }
    };

    // X register prefetch for tile 0
    float4 xv[4];
    {
        const float4* src = (const float4*)(x + (size_t)(m0 + xr) * DD + 0 + xp * 16);
        #pragma unroll
        for (int i = 0; i < 4; i++) xv[i] = src[i];
    }
    stage_w(sb + (uint32_t)(2 * X_ARR), 0);
    CP_COMMIT();

    int wcur = 0;
    for (int k0 = 0; k0 < DD; k0 += GM_BK) {
        __syncthreads();   // X buffer free (previous tile's mma done)

        // store split X (current tile) to smem
        #pragma unroll
        for (int i = 0; i < 4; i++) {
            const int o = xr * XLD + xp * 16 + i * 4;
            uint32_t h0, l0, h1, l1;
            split2(xv[i].x, xv[i].y, h0, l0);
            split2(xv[i].z, xv[i].w, h1, l1);
            *(uint32_t*)(xhi + o + 0) = h0;
            *(uint32_t*)(xhi + o + 2) = h1;
            *(uint32_t*)(xlo + o + 0) = l0;
            *(uint32_t*)(xlo + o + 2) = l1;
        }

        if (k0 + GM_BK < DD) {
            // prefetch next X tile into registers (overlaps with mma below)
            const float4* src = (const float4*)(x + (size_t)(m0 + xr) * DD + (k0 + GM_BK) + xp * 16);
            #pragma unroll
            for (int i = 0; i < 4; i++) xv[i] = src[i];
            // prefetch next W tile into the other buffer
            stage_w(sb + (uint32_t)(2 * X_ARR + (wcur ^ 1) * WBUF), k0 + GM_BK);
            CP_COMMIT();
            CP_WAIT1();    // current W tile complete; next may stay in flight
        } else {
            CP_WAIT0();
        }
        __syncthreads();

        const uint32_t wbase = sb + (uint32_t)(2 * X_ARR + wcur * WBUF)
                             + (uint32_t)(wn * WLD * 2) + b_off;

        #pragma unroll
        for (int kk = 0; kk < GM_BK; kk += 16) {
            const uint32_t ko = (uint32_t)(kk * 2);
            uint32_t ah[2][4], al[2][4];
            ldsm4(ah[0], xhi_s + ko);
            ldsm4(ah[1], xhi_s + (uint32_t)(16 * XLD * 2) + ko);
            ldsm4(al[0], xlo_s + ko);
            ldsm4(al[1], xlo_s + (uint32_t)(16 * XLD * 2) + ko);

            #pragma unroll
            for (int nj = 0; nj < 6; nj++) {
                uint32_t bh[4], bl[4];
                const uint32_t woff = (uint32_t)(nj * (16 * WLD * 2)) + ko;
                ldsm4(bh, wbase + woff);
                ldsm4(bl, wbase + woff + W_ARR);
                #pragma unroll
                for (int mi = 0; mi < 2; mi++) {
                    mma16816(acc[mi][2*nj],   ah[mi], bh);
                    mma16816(acc[mi][2*nj+1], ah[mi], bh + 2);
                    mma16816(acc[mi][2*nj],   ah[mi], bl);
                    mma16816(acc[mi][2*nj+1], ah[mi], bl + 2);
                    mma16816(acc[mi][2*nj],   al[mi], bh);
                    mma16816(acc[mi][2*nj+1], al[mi], bh + 2);
                }
            }
        }
        wcur ^= 1;
    }

    // ---- epilogue: split to bf16 hi/lo, route to Q/K/V by column ----
    #pragma unroll
    for (int mi = 0; mi < 2; mi++) {
        #pragma unroll
        for (int ni = 0; ni < 12; ni++) {
            const size_t r0 = (size_t)m0 + wm + mi * 16 + g;
            const int    c  = wn + ni * 8 + 2 * t4;
            const int    nb = c >> 6;       // 0=Q 1=K 2=V
            const int    ci = c & 63;
            __nv_bfloat16* dhi = (nb == 0) ? g_Qhi : (nb == 1) ? g_Khi : g_Vhi;
            __nv_bfloat16* dlo = (nb == 0) ? g_Qlo : (nb == 1) ? g_Klo : g_Vlo;
            uint32_t h, l;
            split2(acc[mi][ni][0], acc[mi][ni][1], h, l);
            *(uint32_t*)(dhi + r0 * HD + ci) = h;
            *(uint32_t*)(dlo + r0 * HD + ci) = l;
            split2(acc[mi][ni][2], acc[mi][ni][3], h, l);
            *(uint32_t*)(dhi + (r0 + 8) * HD + ci) = h;
            *(uint32_t*)(dlo + (r0 + 8) * HD + ci) = l;
        }
    }
}

// ---------------------------------------------------------------------------
// Kernel 2: split-K causal flash attention, cp.async double-buffered. CK=512.
// (Unchanged from R12.)
// ---------------------------------------------------------------------------
#define TLD 72
#define ARR_B  (64 * TLD * 2)
#define BUF_B  (4 * ARR_B)
#define ATTN_SMEM (2 * BUF_B)

__global__ __launch_bounds__(128, 3) void attn_mma()
{
    extern __shared__ char dsm[];

    const int chunk = blockIdx.x;
    const int tile  = blockIdx.y;
    const int b     = blockIdx.z;

    const int kmax = (tile + 1) * QT;
    const int nch  = (kmax + CK - 1) / CK;
    if (chunk >= nch) return;

    const int kstart = chunk * CK;
    const int kend   = min(kstart + CK, kmax);
    const int q0     = tile * QT;

    const int tid  = threadIdx.x;
    const int warp = tid >> 5;
    const int lane = tid & 31;
    const int g    = lane >> 2;
    const int t4   = lane & 3;

    const size_t boff = (size_t)b * TT_SEQ * HD;
    const uint32_t sb = (uint32_t)__cvta_generic_to_shared(dsm);

    const int la = lane >> 3;
    const int lr = lane & 7;
    const uint32_t k_lane_off = (uint32_t)((((la >> 1) * 8 + lr) * TLD + (la & 1) * 8) * 2);
    const uint32_t v_lane_off = (uint32_t)((((la & 1) * 8 + lr) * TLD + (la >> 1) * 8) * 2);

    uint32_t Qh[2][4][4], Ql[2][4][4];
    #pragma unroll
    for (int mi = 0; mi < 2; mi++) {
        const size_t ar = boff + (size_t)(q0 + warp * 32 + mi * 16 + g) * HD;
        #pragma unroll
        for (int ks = 0; ks < 4; ks++) {
            const int c = ks * 16 + 2 * t4;
            Qh[mi][ks][0] = *(const uint32_t*)(g_Qhi + ar + c);
            Qh[mi][ks][1] = *(const uint32_t*)(g_Qhi + ar + 8 * HD + c);
            Qh[mi][ks][2] = *(const uint32_t*)(g_Qhi + ar + c + 8);
            Qh[mi][ks][3] = *(const uint32_t*)(g_Qhi + ar + 8 * HD + c + 8);
            Ql[mi][ks][0] = *(const uint32_t*)(g_Qlo + ar + c);
            Ql[mi][ks][1] = *(const uint32_t*)(g_Qlo + ar + 8 * HD + c);
            Ql[mi][ks][2] = *(const uint32_t*)(g_Qlo + ar + c + 8);
            Ql[mi][ks][3] = *(const uint32_t*)(g_Qlo + ar + 8 * HD + c + 8);
        }
    }

    float o[2][8][4];
    #pragma unroll
    for (int mi = 0; mi < 2; mi++)
        #pragma unroll
        for (int ni = 0; ni < 8; ni++)
            #pragma unroll
            for (int e = 0; e < 4; e++) o[mi][ni][e] = 0.f;
    float m_[2][2] = {{-1e20f, -1e20f}, {-1e20f, -1e20f}};
    float l_[2][2] = {{0.f, 0.f}, {0.f, 0.f}};

    auto stage_tile = [&](uint32_t sbase, int k0) {
        #pragma unroll
        for (int i = 0; i < 4; i++) {
            const int idx = i * 128 + tid;
            const int row = idx >> 3;
            const int seg = (idx & 7) * 8;
            const size_t gsrc = boff + (size_t)(k0 + row) * HD + seg;
            const uint32_t sdst = sbase + (uint32_t)((row * TLD + seg) * 2);
            CP_ASYNC16(sdst + 0 * ARR_B, g_Khi + gsrc);
            CP_ASYNC16(sdst + 1 * ARR_B, g_Klo + gsrc);
            CP_ASYNC16(sdst + 2 * ARR_B, g_Vhi + gsrc);
            CP_ASYNC16(sdst + 3 * ARR_B, g_Vlo + gsrc);
        }
    };

    stage_tile(sb, kstart);
    CP_COMMIT();

    int cur = 0;
    for (int k0 = kstart; k0 < kend; k0 += 64) {
        CP_WAIT0();
        __syncthreads();
        if (k0 + 64 < kend) {
            stage_tile(sb + (uint32_t)((cur ^ 1) * BUF_B), k0 + 64);
            CP_COMMIT();
        }

        const uint32_t bufb  = sb + (uint32_t)(cur * BUF_B);
        const uint32_t khi_s = bufb + 0 * ARR_B + k_lane_off;
        const uint32_t klo_s = bufb + 1 * ARR_B + k_lane_off;
        const uint32_t vhi_s = bufb + 2 * ARR_B + v_lane_off;
        const uint32_t vlo_s = bufb + 3 * ARR_B + v_lane_off;

        #pragma unroll
        for (int mi = 0; mi < 2; mi++) {
            const int rbase = warp * 32 + mi * 16;

            float s[8][4];
            #pragma unroll
            for (int ni = 0; ni < 8; ni++)
                #pragma unroll
                for (int e = 0; e < 4; e++) s[ni][e] = 0.f;

            #pragma unroll
            for (int ks = 0; ks < 4; ks++) {
                #pragma unroll
                for (int p = 0; p < 4; p++) {
                    const uint32_t off = (uint32_t)(p * (16 * TLD * 2) + ks * 32);
                    uint32_t bh[4], bl[4];
                    ldsm4(bh, khi_s + off);
                    ldsm4(bl, klo_s + off);
                    mma16816(s[2*p],   Qh[mi][ks], bh);
                    mma16816(s[2*p],   Qh[mi][ks], bl);
                    mma16816(s[2*p],   Ql[mi][ks], bh);
                    mma16816(s[2*p+1], Qh[mi][ks], bh + 2);
                    mma16816(s[2*p+1], Qh[mi][ks], bl + 2);
                    mma16816(s[2*p+1], Ql[mi][ks], bh + 2);
                }
            }

            if (k0 + 63 > q0 + rbase) {
                const int qa = q0 + rbase + g;
                #pragma unroll
                for (int ni = 0; ni < 8; ni++) {
                    const int kc = k0 + ni * 8 + 2 * t4;
                    if (kc     > qa)     s[ni][0] = -1e30f;
                    if (kc + 1 > qa)     s[ni][1] = -1e30f;
                    if (kc     > qa + 8) s[ni][2] = -1e30f;
                    if (kc + 1 > qa + 8) s[ni][3] = -1e30f;
                }
            }

            float mxA = -1e30f, mxB = -1e30f;
            #pragma unroll
            for (int ni = 0; ni < 8; ni++) {
                mxA = fmaxf(mxA, fmaxf(s[ni][0], s[ni][1]));
                mxB = fmaxf(mxB, fmaxf(s[ni][2], s[ni][3]));
            }
            mxA = fmaxf(mxA, __shfl_xor_sync(0xffffffffu, mxA, 1));
            mxA = fmaxf(mxA, __shfl_xor_sync(0xffffffffu, mxA, 2));
            mxB = fmaxf(mxB, __shfl_xor_sync(0xffffffffu, mxB, 1));
            mxB = fmaxf(mxB, __shfl_xor_sync(0xffffffffu, mxB, 2));

            const float mA = fmaxf(m_[mi][0], mxA);
            const float mB = fmaxf(m_[mi][1], mxB);
            const float scA = __expf(m_[mi][0] - mA);
            const float scB = __expf(m_[mi][1] - mB);
            m_[mi][0] = mA; m_[mi][1] = mB;

            uint32_t Ph[4][4], Pl[4][4];
            float sA = 0.f, sB = 0.f;
            #pragma unroll
            for (int ni = 0; ni < 8; ni++) {
                float p0 = __expf(s[ni][0] - mA);
                float p1 = __expf(s[ni][1] - mA);
                float p2 = __expf(s[ni][2] - mB);
                float p3 = __expf(s[ni][3] - mB);
                sA += p0 + p1; sB += p2 + p3;
                const int ks   = ni >> 1;
                const int base = (ni & 1) * 2;
                split2(p0, p1, Ph[ks][base + 0], Pl[ks][base + 0]);
                split2(p2, p3, Ph[ks][base + 1], Pl[ks][base + 1]);
            }
            sA += __shfl_xor_sync(0xffffffffu, sA, 1);
            sA += __shfl_xor_sync(0xffffffffu, sA, 2);
            sB += __shfl_xor_sync(0xffffffffu, sB, 1);
            sB += __shfl_xor_sync(0xffffffffu, sB, 2);
            l_[mi][0] = l_[mi][0] * scA + sA;
            l_[mi][1] = l_[mi][1] * scB + sB;

            #pragma unroll
            for (int ni = 0; ni < 8; ni++) {
                o[mi][ni][0] *= scA; o[mi][ni][1] *= scA;
                o[mi][ni][2] *= scB; o[mi][ni][3] *= scB;
            }

            #pragma unroll
            for (int ks = 0; ks < 4; ks++) {
                #pragma unroll
                for (int p = 0; p < 4; p++) {
                    const uint32_t off = (uint32_t)(ks * (16 * TLD * 2) + p * 32);
                    uint32_t bh[4], bl[4];
                    ldsm4t(bh, vhi_s + off);
                    ldsm4t(bl, vlo_s + off);
                    mma16816(o[mi][2*p],   Ph[ks], bh);
                    mma16816(o[mi][2*p],   Ph[ks], bl);
                    mma16816(o[mi][2*p],   Pl[ks], bh);
                    mma16816(o[mi][2*p+1], Ph[ks], bh + 2);
                    mma16816(o[mi][2*p+1], Ph[ks], bl + 2);
                    mma16816(o[mi][2*p+1], Pl[ks], bh + 2);
                }
            }
        }
        __syncthreads();
        cur ^= 1;
    }

    const size_t pbase = ((size_t)(b * TILES + tile) * NCH_MAX + chunk) * QT;
    #pragma unroll
    for (int mi = 0; mi < 2; mi++) {
        const int lrA = warp * 32 + mi * 16 + g;
        if (t4 == 0) {
            g_pm[pbase + lrA]     = m_[mi][0];
            g_pl[pbase + lrA]     = l_[mi][0];
            g_pm[pbase + lrA + 8] = m_[mi][1];
            g_pl[pbase + lrA + 8] = l_[mi][1];
        }
        #pragma unroll
        for (int ni = 0; ni < 8; ni++) {
            const int c = ni * 8 + 2 * t4;
            float2 vA, vB;
            vA.x = o[mi][ni][0]; vA.y = o[mi][ni][1];
            vB.x = o[mi][ni][2]; vB.y = o[mi][ni][3];
            *(float2*)(g_pacc + (pbase + lrA) * HD + c)       = vA;
            *(float2*)(g_pacc + (pbase + lrA + 8) * HD + c)   = vB;
        }
    }
}

// ---------------------------------------------------------------------------
// Kernel 3: combine split-K partials, float4 vectorized.
// ---------------------------------------------------------------------------
__global__ __launch_bounds__(256) void combine_kernel(float* __restrict__ out)
{
    const int gid = blockIdx.x * 256 + threadIdx.x;
    const int q   = gid >> 4;
    const int d   = (gid & 15) * 4;

    const int b      = q / TT_SEQ;
    const int t_in_b = q % TT_SEQ;
    const int tile   = t_in_b / QT;
    const int qi     = t_in_b % QT;

    const int kmax = (tile + 1) * QT;
    const int nch  = (kmax + CK - 1) / CK;

    const size_t base = ((size_t)(b * TILES + tile) * NCH_MAX) * QT + qi;

    float mstar = -1e30f;
    for (int i = 0; i < nch; i++) {
        float mi = g_pm[base + (size_t)i * QT];
        mstar = fmaxf(mstar, mi);
    }

    float L = 0.f;
    float4 val = make_float4(0.f, 0.f, 0.f, 0.f);
    for (int i = 0; i < nch; i++) {
        const size_t pidx = base + (size_t)i * QT;
        float w = __expf(g_pm[pidx] - mstar);
        L += g_pl[pidx] * w;
        float4 a = *(const float4*)(g_pacc + pidx * HD + d);
        val.x += a.x * w; val.y += a.y * w;
        val.z += a.z * w; val.w += a.w * w;
    }

    const float inv = 1.f / L;
    float4 r;
    r.x = val.x * inv; r.y = val.y * inv; r.z = val.z * inv; r.w = val.w * inv;
    *(float4*)(out + (size_t)q * HD + d) = r;
}

extern "C" void kernel_launch(void* const* d_in, const int* in_sizes, int n_in,
                              void* d_out, int out_size)
{
    const float* x  = (const float*)d_in[0];
    const float* Wq = (const float*)d_in[1];
    const float* Wk = (const float*)d_in[2];
    const float* Wv = (const float*)d_in[3];
    float* out = (float*)d_out;

    cudaFuncSetAttribute(qkv_fused, cudaFuncAttributeMaxDynamicSharedMemorySize, QKV_SMEM);
    cudaFuncSetAttribute(attn_mma, cudaFuncAttributeMaxDynamicSharedMemorySize, ATTN_SMEM);

    convert_w<<<(3 * HD * DD / 4) / 256, 256>>>(Wq, Wk, Wv);

    qkv_fused<<<NTOK / GM_BM, 128, QKV_SMEM>>>(x);

    dim3 agrid(NCH_MAX, TILES, BB);
    attn_mma<<<agrid, 128, ATTN_SMEM>>>();

    combine_kernel<<<(NTOK * 16) / 256, 256>>>(out);
}

// round 14
// speedup vs baseline: 1.1508x; 1.1508x over previous
#include <cuda_runtime.h>
#include <cuda_bf16.h>
#include <math.h>
#include <stdint.h>

#define BB 4
#define TT_SEQ 4096
#define DD 1024
#define HD 64
#define NTOK (BB*TT_SEQ)

#define QT 128
#define CK 512
#define TILES (TT_SEQ/QT)      // 32
#define NCH_MAX (TT_SEQ/CK)    // 8

// W in bf16 hi/lo, rows 0-63=Wq(*0.125), 64-127=Wk, 128-191=Wv
__device__ __nv_bfloat16 g_Whi[3*HD*DD];
__device__ __nv_bfloat16 g_Wlo[3*HD*DD];

// Q/K/V stored ONLY as packed bf16 hi/lo. Q pre-scaled by hd^-0.5.
__device__ __nv_bfloat16 g_Qhi[NTOK*HD];
__device__ __nv_bfloat16 g_Qlo[NTOK*HD];
__device__ __nv_bfloat16 g_Khi[NTOK*HD];
__device__ __nv_bfloat16 g_Klo[NTOK*HD];
__device__ __nv_bfloat16 g_Vhi[NTOK*HD];
__device__ __nv_bfloat16 g_Vlo[NTOK*HD];

// Split-K partials
__device__ float g_pacc[BB*TILES*NCH_MAX*QT*HD];
__device__ float g_pm  [BB*TILES*NCH_MAX*QT];
__device__ float g_pl  [BB*TILES*NCH_MAX*QT];

__device__ __forceinline__ uint32_t pack_bf16(float a, float b) {
    __nv_bfloat162 t = __floats2bfloat162_rn(a, b);
    return *reinterpret_cast<uint32_t*>(&t);
}

__device__ __forceinline__ void split2(float a, float b, uint32_t& hi, uint32_t& lo) {
    __nv_bfloat162 h = __floats2bfloat162_rn(a, b);
    hi = *reinterpret_cast<uint32_t*>(&h);
    lo = pack_bf16(a - __bfloat162float(h.x), b - __bfloat162float(h.y));
}

__device__ __forceinline__ void mma16816(float* d, const uint32_t* a, const uint32_t* b) {
    asm volatile(
        "mma.sync.aligned.m16n8k16.row.col.f32.bf16.bf16.f32 "
        "{%0,%1,%2,%3}, {%4,%5,%6,%7}, {%8,%9}, {%0,%1,%2,%3};"
        : "+f"(d[0]), "+f"(d[1]), "+f"(d[2]), "+f"(d[3])
        : "r"(a[0]), "r"(a[1]), "r"(a[2]), "r"(a[3]),
          "r"(b[0]), "r"(b[1]));
}

__device__ __forceinline__ void ldsm4(uint32_t* d, uint32_t addr) {
    asm volatile("ldmatrix.sync.aligned.m8n8.x4.shared.b16 {%0,%1,%2,%3}, [%4];"
        : "=r"(d[0]), "=r"(d[1]), "=r"(d[2]), "=r"(d[3]) : "r"(addr));
}
__device__ __forceinline__ void ldsm4t(uint32_t* d, uint32_t addr) {
    asm volatile("ldmatrix.sync.aligned.m8n8.x4.trans.shared.b16 {%0,%1,%2,%3}, [%4];"
        : "=r"(d[0]), "=r"(d[1]), "=r"(d[2]), "=r"(d[3]) : "r"(addr));
}

#define CP_ASYNC16(saddr, gptr) \
    asm volatile("cp.async.cg.shared.global [%0], [%1], 16;" :: "r"(saddr), "l"(gptr) : "memory")
#define CP_COMMIT() asm volatile("cp.async.commit_group;" ::: "memory")
#define CP_WAIT0()  asm volatile("cp.async.wait_group 0;" ::: "memory")
#define CP_WAIT1()  asm volatile("cp.async.wait_group 1;" ::: "memory")

// ---------------------------------------------------------------------------
// Kernel 0: convert W (fp32 -> bf16 hi/lo), fold 1/8 into Wq.
// ---------------------------------------------------------------------------
__global__ __launch_bounds__(256) void convert_w(
    const float* __restrict__ Wq,
    const float* __restrict__ Wk,
    const float* __restrict__ Wv)
{
    const int idx = blockIdx.x * 256 + threadIdx.x;
    const int e0  = idx * 4;
    const int row = e0 >> 10;
    const int col = e0 & 1023;
    const float* src = (row < 64) ? Wq + (size_t)row * DD
                     : (row < 128) ? Wk + (size_t)(row - 64) * DD
                                   : Wv + (size_t)(row - 128) * DD;
    const float sc = (row < 64) ? 0.125f : 1.0f;
    float4 v = *(const float4*)(src + col);
    v.x *= sc; v.y *= sc; v.z *= sc; v.w *= sc;

    uint2 hi, lo;
    split2(v.x, v.y, hi.x, lo.x);
    split2(v.z, v.w, hi.y, lo.y);

    *(uint2*)(g_Whi + e0) = hi;
    *(uint2*)(g_Wlo + e0) = lo;
}

// ---------------------------------------------------------------------------
// Kernel 1: FUSED QKV projection (R12 configuration: BM=128, 256 threads).
// One CTA = 128 tokens x all 192 outputs. X loaded fp32 + split once per
// tile (register-prefetched, single buffer); W double-buffered via cp.async.
// 8 warps in 4(M)x2(N), warp tile 32x96.
// ---------------------------------------------------------------------------
#define GM_BM 128
#define GM_BK 32
#define XLD 40
#define WLD 40
#define X_ARR (GM_BM * XLD * 2)        // 10240 B (one of hi/lo)
#define W_ARR (192 * WLD * 2)          // 15360 B
#define WBUF  (2 * W_ARR)              // 30720 B
#define QKV_SMEM (2 * X_ARR + 2 * WBUF)  // 81920 B

__global__ __launch_bounds__(256, 1) void qkv_fused(const float* __restrict__ x)
{
    extern __shared__ char qsm[];
    __nv_bfloat16* xhi = (__nv_bfloat16*)qsm;
    __nv_bfloat16* xlo = (__nv_bfloat16*)(qsm + X_ARR);

    const int m0 = blockIdx.x * GM_BM;

    const int tid  = threadIdx.x;
    const int warp = tid >> 5;
    const int lane = tid & 31;
    const int wm   = (warp & 3) * 32;     // warp M offset
    const int wn   = (warp >> 2) * 96;    // warp N offset (0 or 96)
    const int g    = lane >> 2;
    const int t4   = lane & 3;

    const int la = lane >> 3;
    const int lr = lane & 7;
    const uint32_t a_off = (uint32_t)((((la & 1) * 8 + lr) * XLD + (la >> 1) * 8) * 2);
    const uint32_t b_off = (uint32_t)((((la >> 1) * 8 + lr) * WLD + (la & 1) * 8) * 2);

    const uint32_t sb    = (uint32_t)__cvta_generic_to_shared(qsm);
    const uint32_t xhi_s = sb + (uint32_t)(wm * XLD * 2) + a_off;
    const uint32_t xlo_s = xhi_s + X_ARR;

    float acc[2][12][4];
    #pragma unroll
    for (int mi = 0; mi < 2; mi++)
        #pragma unroll
        for (int ni = 0; ni < 12; ni++)
            #pragma unroll
            for (int e = 0; e < 4; e++) acc[mi][ni][e] = 0.f;

    const int xr = tid >> 1;       // X row this thread stages
    const int xp = tid & 1;        // 16-float half

    // W staging: 768 16B-slots per array, 3 per thread
    auto stage_w = [&](uint32_t wbase, int k0) {
        #pragma unroll
        for (int i = 0; i < 3; i++) {
            const int s   = i * 256 + tid;
            const int row = s >> 2;
            const int seg = (s & 3) * 8;
            const size_t gof = (size_t)row * DD + k0 + seg;
            const uint32_t sdst = wbase + (uint32_t)((row * WLD + seg) * 2);
            CP_ASYNC16(sdst,         g_Whi + gof);
            CP_ASYNC16(sdst + W_ARR, g_Wlo + gof);
        }
    };

    // X register prefetch for tile 0
    float4 xv[4];
    {
        const float4* src = (const float4*)(x + (size_t)(m0 + xr) * DD + 0 + xp * 16);
        #pragma unroll
        for (int i = 0; i < 4; i++) xv[i] = src[i];
    }
    stage_w(sb + (uint32_t)(2 * X_ARR), 0);
    CP_COMMIT();

    int wcur = 0;
    for (int k0 = 0; k0 < DD; k0 += GM_BK) {
        __syncthreads();   // X buffer free (previous tile's mma done)

        // store split X (current tile) to smem
        #pragma unroll
        for (int i = 0; i < 4; i++) {
            const int o = xr * XLD + xp * 16 + i * 4;
            uint32_t h0, l0, h1, l1;
            split2(xv[i].x, xv[i].y, h0, l0);
            split2(xv[i].z, xv[i].w, h1, l1);
            *(uint32_t*)(xhi + o + 0) = h0;
            *(uint32_t*)(xhi + o + 2) = h1;
            *(uint32_t*)(xlo + o + 0) = l0;
            *(uint32_t*)(xlo + o + 2) = l1;
        }

        if (k0 + GM_BK < DD) {
            // prefetch next X tile into registers (overlaps with mma below)
            const float4* src = (const float4*)(x + (size_t)(m0 + xr) * DD + (k0 + GM_BK) + xp * 16);
            #pragma unroll
            for (int i = 0; i < 4; i++) xv[i] = src[i];
            // prefetch next W tile into the other buffer
            stage_w(sb + (uint32_t)(2 * X_ARR + (wcur ^ 1) * WBUF), k0 + GM_BK);
            CP_COMMIT();
            CP_WAIT1();    // current W tile complete; next may stay in flight
        } else {
            CP_WAIT0();
        }
        __syncthreads();

        const uint32_t wbase = sb + (uint32_t)(2 * X_ARR + wcur * WBUF)
                             + (uint32_t)(wn * WLD * 2) + b_off;

        #pragma unroll
        for (int kk = 0; kk < GM_BK; kk += 16) {
            const uint32_t ko = (uint32_t)(kk * 2);
            uint32_t ah[2][4], al[2][4];
            ldsm4(ah[0], xhi_s + ko);
            ldsm4(ah[1], xhi_s + (uint32_t)(16 * XLD * 2) + ko);
            ldsm4(al[0], xlo_s + ko);
            ldsm4(al[1], xlo_s + (uint32_t)(16 * XLD * 2) + ko);

            #pragma unroll
            for (int nj = 0; nj < 6; nj++) {
                uint32_t bh[4], bl[4];
                const uint32_t woff = (uint32_t)(nj * (16 * WLD * 2)) + ko;
                ldsm4(bh, wbase + woff);
                ldsm4(bl, wbase + woff + W_ARR);
                #pragma unroll
                for (int mi = 0; mi < 2; mi++) {
                    mma16816(acc[mi][2*nj],   ah[mi], bh);
                    mma16816(acc[mi][2*nj+1], ah[mi], bh + 2);
                    mma16816(acc[mi][2*nj],   ah[mi], bl);
                    mma16816(acc[mi][2*nj+1], ah[mi], bl + 2);
                    mma16816(acc[mi][2*nj],   al[mi], bh);
                    mma16816(acc[mi][2*nj+1], al[mi], bh + 2);
                }
            }
        }
        wcur ^= 1;
    }

    // ---- epilogue: split to bf16 hi/lo, route to Q/K/V by column ----
    #pragma unroll
    for (int mi = 0; mi < 2; mi++) {
        #pragma unroll
        for (int ni = 0; ni < 12; ni++) {
            const size_t r0 = (size_t)m0 + wm + mi * 16 + g;
            const int    c  = wn + ni * 8 + 2 * t4;
            const int    nb = c >> 6;       // 0=Q 1=K 2=V
            const int    ci = c & 63;
            __nv_bfloat16* dhi = (nb == 0) ? g_Qhi : (nb == 1) ? g_Khi : g_Vhi;
            __nv_bfloat16* dlo = (nb == 0) ? g_Qlo : (nb == 1) ? g_Klo : g_Vlo;
            uint32_t h, l;
            split2(acc[mi][ni][0], acc[mi][ni][1], h, l);
            *(uint32_t*)(dhi + r0 * HD + ci) = h;
            *(uint32_t*)(dlo + r0 * HD + ci) = l;
            split2(acc[mi][ni][2], acc[mi][ni][3], h, l);
            *(uint32_t*)(dhi + (r0 + 8) * HD + ci) = h;
            *(uint32_t*)(dlo + (r0 + 8) * HD + ci) = l;
        }
    }
}

// ---------------------------------------------------------------------------
// Kernel 2: split-K causal flash attention, cp.async double-buffered. CK=512.
// NO min-blocks clause (natural 255 regs, no spills). Heavy tiles first.
// ---------------------------------------------------------------------------
#define TLD 72
#define ARR_B  (64 * TLD * 2)
#define BUF_B  (4 * ARR_B)
#define ATTN_SMEM (2 * BUF_B)

__global__ __launch_bounds__(128) void attn_mma()
{
    extern __shared__ char dsm[];

    const int chunk = blockIdx.x;
    const int tile  = (TILES - 1) - blockIdx.y;   // heavy tiles launch first
    const int b     = blockIdx.z;

    const int kmax = (tile + 1) * QT;
    const int nch  = (kmax + CK - 1) / CK;
    if (chunk >= nch) return;

    const int kstart = chunk * CK;
    const int kend   = min(kstart + CK, kmax);
    const int q0     = tile * QT;

    const int tid  = threadIdx.x;
    const int warp = tid >> 5;
    const int lane = tid & 31;
    const int g    = lane >> 2;
    const int t4   = lane & 3;

    const size_t boff = (size_t)b * TT_SEQ * HD;
    const uint32_t sb = (uint32_t)__cvta_generic_to_shared(dsm);

    const int la = lane >> 3;
    const int lr = lane & 7;
    const uint32_t k_lane_off = (uint32_t)((((la >> 1) * 8 + lr) * TLD + (la & 1) * 8) * 2);
    const uint32_t v_lane_off = (uint32_t)((((la & 1) * 8 + lr) * TLD + (la >> 1) * 8) * 2);

    uint32_t Qh[2][4][4], Ql[2][4][4];
    #pragma unroll
    for (int mi = 0; mi < 2; mi++) {
        const size_t ar = boff + (size_t)(q0 + warp * 32 + mi * 16 + g) * HD;
        #pragma unroll
        for (int ks = 0; ks < 4; ks++) {
            const int c = ks * 16 + 2 * t4;
            Qh[mi][ks][0] = *(const uint32_t*)(g_Qhi + ar + c);
            Qh[mi][ks][1] = *(const uint32_t*)(g_Qhi + ar + 8 * HD + c);
            Qh[mi][ks][2] = *(const uint32_t*)(g_Qhi + ar + c + 8);
            Qh[mi][ks][3] = *(const uint32_t*)(g_Qhi + ar + 8 * HD + c + 8);
            Ql[mi][ks][0] = *(const uint32_t*)(g_Qlo + ar + c);
            Ql[mi][ks][1] = *(const uint32_t*)(g_Qlo + ar + 8 * HD + c);
            Ql[mi][ks][2] = *(const uint32_t*)(g_Qlo + ar + c + 8);
            Ql[mi][ks][3] = *(const uint32_t*)(g_Qlo + ar + 8 * HD + c + 8);
        }
    }

    float o[2][8][4];
    #pragma unroll
    for (int mi = 0; mi < 2; mi++)
        #pragma unroll
        for (int ni = 0; ni < 8; ni++)
            #pragma unroll
            for (int e = 0; e < 4; e++) o[mi][ni][e] = 0.f;
    float m_[2][2] = {{-1e20f, -1e20f}, {-1e20f, -1e20f}};
    float l_[2][2] = {{0.f, 0.f}, {0.f, 0.f}};

    auto stage_tile = [&](uint32_t sbase, int k0) {
        #pragma unroll
        for (int i = 0; i < 4; i++) {
            const int idx = i * 128 + tid;
            const int row = idx >> 3;
            const int seg = (idx & 7) * 8;
            const size_t gsrc = boff + (size_t)(k0 + row) * HD + seg;
            const uint32_t sdst = sbase + (uint32_t)((row * TLD + seg) * 2);
            CP_ASYNC16(sdst + 0 * ARR_B, g_Khi + gsrc);
            CP_ASYNC16(sdst + 1 * ARR_B, g_Klo + gsrc);
            CP_ASYNC16(sdst + 2 * ARR_B, g_Vhi + gsrc);
            CP_ASYNC16(sdst + 3 * ARR_B, g_Vlo + gsrc);
        }
    };

    stage_tile(sb, kstart);
    CP_COMMIT();

    int cur = 0;
    for (int k0 = kstart; k0 < kend; k0 += 64) {
        CP_WAIT0();
        __syncthreads();
        if (k0 + 64 < kend) {
            stage_tile(sb + (uint32_t)((cur ^ 1) * BUF_B), k0 + 64);
            CP_COMMIT();
        }

        const uint32_t bufb  = sb + (uint32_t)(cur * BUF_B);
        const uint32_t khi_s = bufb + 0 * ARR_B + k_lane_off;
        const uint32_t klo_s = bufb + 1 * ARR_B + k_lane_off;
        const uint32_t vhi_s = bufb + 2 * ARR_B + v_lane_off;
        const uint32_t vlo_s = bufb + 3 * ARR_B + v_lane_off;

        #pragma unroll
        for (int mi = 0; mi < 2; mi++) {
            const int rbase = warp * 32 + mi * 16;

            float s[8][4];
            #pragma unroll
            for (int ni = 0; ni < 8; ni++)
                #pragma unroll
                for (int e = 0; e < 4; e++) s[ni][e] = 0.f;

            #pragma unroll
            for (int ks = 0; ks < 4; ks++) {
                #pragma unroll
                for (int p = 0; p < 4; p++) {
                    const uint32_t off = (uint32_t)(p * (16 * TLD * 2) + ks * 32);
                    uint32_t bh[4], bl[4];
                    ldsm4(bh, khi_s + off);
                    ldsm4(bl, klo_s + off);
                    mma16816(s[2*p],   Qh[mi][ks], bh);
                    mma16816(s[2*p],   Qh[mi][ks], bl);
                    mma16816(s[2*p],   Ql[mi][ks], bh);
                    mma16816(s[2*p+1], Qh[mi][ks], bh + 2);
                    mma16816(s[2*p+1], Qh[mi][ks], bl + 2);
                    mma16816(s[2*p+1], Ql[mi][ks], bh + 2);
                }
            }

            if (k0 + 63 > q0 + rbase) {
                const int qa = q0 + rbase + g;
                #pragma unroll
                for (int ni = 0; ni < 8; ni++) {
                    const int kc = k0 + ni * 8 + 2 * t4;
                    if (kc     > qa)     s[ni][0] = -1e30f;
                    if (kc + 1 > qa)     s[ni][1] = -1e30f;
                    if (kc     > qa + 8) s[ni][2] = -1e30f;
                    if (kc + 1 > qa + 8) s[ni][3] = -1e30f;
                }
            }

            float mxA = -1e30f, mxB = -1e30f;
            #pragma unroll
            for (int ni = 0; ni < 8; ni++) {
                mxA = fmaxf(mxA, fmaxf(s[ni][0], s[ni][1]));
                mxB = fmaxf(mxB, fmaxf(s[ni][2], s[ni][3]));
            }
            mxA = fmaxf(mxA, __shfl_xor_sync(0xffffffffu, mxA, 1));
            mxA = fmaxf(mxA, __shfl_xor_sync(0xffffffffu, mxA, 2));
            mxB = fmaxf(mxB, __shfl_xor_sync(0xffffffffu, mxB, 1));
            mxB = fmaxf(mxB, __shfl_xor_sync(0xffffffffu, mxB, 2));

            const float mA = fmaxf(m_[mi][0], mxA);
            const float mB = fmaxf(m_[mi][1], mxB);
            const float scA = __expf(m_[mi][0] - mA);
            const float scB = __expf(m_[mi][1] - mB);
            m_[mi][0] = mA; m_[mi][1] = mB;

            uint32_t Ph[4][4], Pl[4][4];
            float sA = 0.f, sB = 0.f;
            #pragma unroll
            for (int ni = 0; ni < 8; ni++) {
                float p0 = __expf(s[ni][0] - mA);
                float p1 = __expf(s[ni][1] - mA);
                float p2 = __expf(s[ni][2] - mB);
                float p3 = __expf(s[ni][3] - mB);
                sA += p0 + p1; sB += p2 + p3;
                const int ks   = ni >> 1;
                const int base = (ni & 1) * 2;
                split2(p0, p1, Ph[ks][base + 0], Pl[ks][base + 0]);
                split2(p2, p3, Ph[ks][base + 1], Pl[ks][base + 1]);
            }
            sA += __shfl_xor_sync(0xffffffffu, sA, 1);
            sA += __shfl_xor_sync(0xffffffffu, sA, 2);
            sB += __shfl_xor_sync(0xffffffffu, sB, 1);
            sB += __shfl_xor_sync(0xffffffffu, sB, 2);
            l_[mi][0] = l_[mi][0] * scA + sA;
            l_[mi][1] = l_[mi][1] * scB + sB;

            #pragma unroll
            for (int ni = 0; ni < 8; ni++) {
                o[mi][ni][0] *= scA; o[mi][ni][1] *= scA;
                o[mi][ni][2] *= scB; o[mi][ni][3] *= scB;
            }

            #pragma unroll
            for (int ks = 0; ks < 4; ks++) {
                #pragma unroll
                for (int p = 0; p < 4; p++) {
                    const uint32_t off = (uint32_t)(ks * (16 * TLD * 2) + p * 32);
                    uint32_t bh[4], bl[4];
                    ldsm4t(bh, vhi_s + off);
                    ldsm4t(bl, vlo_s + off);
                    mma16816(o[mi][2*p],   Ph[ks], bh);
                    mma16816(o[mi][2*p],   Ph[ks], bl);
                    mma16816(o[mi][2*p],   Pl[ks], bh);
                    mma16816(o[mi][2*p+1], Ph[ks], bh + 2);
                    mma16816(o[mi][2*p+1], Ph[ks], bl + 2);
                    mma16816(o[mi][2*p+1], Pl[ks], bh + 2);
                }
            }
        }
        __syncthreads();
        cur ^= 1;
    }

    const size_t pbase = ((size_t)(b * TILES + tile) * NCH_MAX + chunk) * QT;
    #pragma unroll
    for (int mi = 0; mi < 2; mi++) {
        const int lrA = warp * 32 + mi * 16 + g;
        if (t4 == 0) {
            g_pm[pbase + lrA]     = m_[mi][0];
            g_pl[pbase + lrA]     = l_[mi][0];
            g_pm[pbase + lrA + 8] = m_[mi][1];
            g_pl[pbase + lrA + 8] = l_[mi][1];
        }
        #pragma unroll
        for (int ni = 0; ni < 8; ni++) {
            const int c = ni * 8 + 2 * t4;
            float2 vA, vB;
            vA.x = o[mi][ni][0]; vA.y = o[mi][ni][1];
            vB.x = o[mi][ni][2]; vB.y = o[mi][ni][3];
            *(float2*)(g_pacc + (pbase + lrA) * HD + c)       = vA;
            *(float2*)(g_pacc + (pbase + lrA + 8) * HD + c)   = vB;
        }
    }
}

// ---------------------------------------------------------------------------
// Kernel 3: combine split-K partials, float4 vectorized.
// ---------------------------------------------------------------------------
__global__ __launch_bounds__(256) void combine_kernel(float* __restrict__ out)
{
    const int gid = blockIdx.x * 256 + threadIdx.x;
    const int q   = gid >> 4;
    const int d   = (gid & 15) * 4;

    const int b      = q / TT_SEQ;
    const int t_in_b = q % TT_SEQ;
    const int tile   = t_in_b / QT;
    const int qi     = t_in_b % QT;

    const int kmax = (tile + 1) * QT;
    const int nch  = (kmax + CK - 1) / CK;

    const size_t base = ((size_t)(b * TILES + tile) * NCH_MAX) * QT + qi;

    float mstar = -1e30f;
    for (int i = 0; i < nch; i++) {
        float mi = g_pm[base + (size_t)i * QT];
        mstar = fmaxf(mstar, mi);
    }

    float L = 0.f;
    float4 val = make_float4(0.f, 0.f, 0.f, 0.f);
    for (int i = 0; i < nch; i++) {
        const size_t pidx = base + (size_t)i * QT;
        float w = __expf(g_pm[pidx] - mstar);
        L += g_pl[pidx] * w;
        float4 a = *(const float4*)(g_pacc + pidx * HD + d);
        val.x += a.x * w; val.y += a.y * w;
        val.z += a.z * w; val.w += a.w * w;
    }

    const float inv = 1.f / L;
    float4 r;
    r.x = val.x * inv; r.y = val.y * inv; r.z = val.z * inv; r.w = val.w * inv;
    *(float4*)(out + (size_t)q * HD + d) = r;
}

extern "C" void kernel_launch(void* const* d_in, const int* in_sizes, int n_in,
                              void* d_out, int out_size)
{
    const float* x  = (const float*)d_in[0];
    const float* Wq = (const float*)d_in[1];
    const float* Wk = (const float*)d_in[2];
    const float* Wv = (const float*)d_in[3];
    float* out = (float*)d_out;

    cudaFuncSetAttribute(qkv_fused, cudaFuncAttributeMaxDynamicSharedMemorySize, QKV_SMEM);
    cudaFuncSetAttribute(attn_mma, cudaFuncAttributeMaxDynamicSharedMemorySize, ATTN_SMEM);

    convert_w<<<(3 * HD * DD / 4) / 256, 256>>>(Wq, Wk, Wv);

    qkv_fused<<<NTOK / GM_BM, 256, QKV_SMEM>>>(x);

    dim3 agrid(NCH_MAX, TILES, BB);
    attn_mma<<<agrid, 128, ATTN_SMEM>>>();

    combine_kernel<<<(NTOK * 16) / 256, 256>>>(out);
}

// round 15
// speedup vs baseline: 1.1522x; 1.0012x over previous
#include <cuda_runtime.h>
#include <cuda_bf16.h>
#include <math.h>
#include <stdint.h>

#define BB 4
#define TT_SEQ 4096
#define DD 1024
#define HD 64
#define NTOK (BB*TT_SEQ)

#define QT 128
#define CK 512
#define TILES (TT_SEQ/QT)      // 32
#define NCH_MAX (TT_SEQ/CK)    // 8

// W in bf16 hi/lo, rows 0-63=Wq(*0.125), 64-127=Wk, 128-191=Wv
__device__ __nv_bfloat16 g_Whi[3*HD*DD];
__device__ __nv_bfloat16 g_Wlo[3*HD*DD];

// Q/K/V stored ONLY as packed bf16 hi/lo. Q pre-scaled by hd^-0.5.
__device__ __nv_bfloat16 g_Qhi[NTOK*HD];
__device__ __nv_bfloat16 g_Qlo[NTOK*HD];
__device__ __nv_bfloat16 g_Khi[NTOK*HD];
__device__ __nv_bfloat16 g_Klo[NTOK*HD];
__device__ __nv_bfloat16 g_Vhi[NTOK*HD];
__device__ __nv_bfloat16 g_Vlo[NTOK*HD];

// Split-K partials
__device__ float g_pacc[BB*TILES*NCH_MAX*QT*HD];
__device__ float g_pm  [BB*TILES*NCH_MAX*QT];
__device__ float g_pl  [BB*TILES*NCH_MAX*QT];

__device__ __forceinline__ uint32_t pack_bf16(float a, float b) {
    __nv_bfloat162 t = __floats2bfloat162_rn(a, b);
    return *reinterpret_cast<uint32_t*>(&t);
}

__device__ __forceinline__ void split2(float a, float b, uint32_t& hi, uint32_t& lo) {
    __nv_bfloat162 h = __floats2bfloat162_rn(a, b);
    hi = *reinterpret_cast<uint32_t*>(&h);
    lo = pack_bf16(a - __bfloat162float(h.x), b - __bfloat162float(h.y));
}

__device__ __forceinline__ void mma16816(float* d, const uint32_t* a, const uint32_t* b) {
    asm volatile(
        "mma.sync.aligned.m16n8k16.row.col.f32.bf16.bf16.f32 "
        "{%0,%1,%2,%3}, {%4,%5,%6,%7}, {%8,%9}, {%0,%1,%2,%3};"
        : "+f"(d[0]), "+f"(d[1]), "+f"(d[2]), "+f"(d[3])
        : "r"(a[0]), "r"(a[1]), "r"(a[2]), "r"(a[3]),
          "r"(b[0]), "r"(b[1]));
}

__device__ __forceinline__ void ldsm4(uint32_t* d, uint32_t addr) {
    asm volatile("ldmatrix.sync.aligned.m8n8.x4.shared.b16 {%0,%1,%2,%3}, [%4];"
        : "=r"(d[0]), "=r"(d[1]), "=r"(d[2]), "=r"(d[3]) : "r"(addr));
}
__device__ __forceinline__ void ldsm4t(uint32_t* d, uint32_t addr) {
    asm volatile("ldmatrix.sync.aligned.m8n8.x4.trans.shared.b16 {%0,%1,%2,%3}, [%4];"
        : "=r"(d[0]), "=r"(d[1]), "=r"(d[2]), "=r"(d[3]) : "r"(addr));
}

#define CP_ASYNC16(saddr, gptr) \
    asm volatile("cp.async.cg.shared.global [%0], [%1], 16;" :: "r"(saddr), "l"(gptr) : "memory")
#define CP_COMMIT() asm volatile("cp.async.commit_group;" ::: "memory")
#define CP_WAIT0()  asm volatile("cp.async.wait_group 0;" ::: "memory")
#define CP_WAIT1()  asm volatile("cp.async.wait_group 1;" ::: "memory")

// ---------------------------------------------------------------------------
// Kernel 0: convert W (fp32 -> bf16 hi/lo), fold 1/8 into Wq.
// ---------------------------------------------------------------------------
__global__ __launch_bounds__(256) void convert_w(
    const float* __restrict__ Wq,
    const float* __restrict__ Wk,
    const float* __restrict__ Wv)
{
    const int idx = blockIdx.x * 256 + threadIdx.x;
    const int e0  = idx * 4;
    const int row = e0 >> 10;
    const int col = e0 & 1023;
    const float* src = (row < 64) ? Wq + (size_t)row * DD
                     : (row < 128) ? Wk + (size_t)(row - 64) * DD
                                   : Wv + (size_t)(row - 128) * DD;
    const float sc = (row < 64) ? 0.125f : 1.0f;
    float4 v = *(const float4*)(src + col);
    v.x *= sc; v.y *= sc; v.z *= sc; v.w *= sc;

    uint2 hi, lo;
    split2(v.x, v.y, hi.x, lo.x);
    split2(v.z, v.w, hi.y, lo.y);

    *(uint2*)(g_Whi + e0) = hi;
    *(uint2*)(g_Wlo + e0) = lo;
}

// ---------------------------------------------------------------------------
// Kernel 1: FUSED QKV projection. BM=64, 256 threads, 2 CTAs/SM, grid=256.
// 8 warps in 2(M)x4(N), warp tile 32x48, acc = 48 floats/thread.
// X loaded fp32 + split once per tile (register-prefetched, single buffer);
// W (preconverted bf16 hi/lo) double-buffered via cp.async.
// ---------------------------------------------------------------------------
#define GM_BM 64
#define GM_BK 32
#define XLD 40
#define WLD 40
#define X_ARR (GM_BM * XLD * 2)        // 5120 B (one of hi/lo)
#define W_ARR (192 * WLD * 2)          // 15360 B
#define WBUF  (2 * W_ARR)              // 30720 B
#define QKV_SMEM (2 * X_ARR + 2 * WBUF)  // 71680 B

__global__ __launch_bounds__(256, 2) void qkv_fused(const float* __restrict__ x)
{
    extern __shared__ char qsm[];
    __nv_bfloat16* xhi = (__nv_bfloat16*)qsm;
    __nv_bfloat16* xlo = (__nv_bfloat16*)(qsm + X_ARR);

    const int m0 = blockIdx.x * GM_BM;

    const int tid  = threadIdx.x;
    const int warp = tid >> 5;
    const int lane = tid & 31;
    const int wm   = (warp & 1) * 32;     // warp M offset (0 or 32)
    const int wn   = (warp >> 1) * 48;    // warp N offset (0,48,96,144)
    const int g    = lane >> 2;
    const int t4   = lane & 3;

    const int la = lane >> 3;
    const int lr = lane & 7;
    const uint32_t a_off = (uint32_t)((((la & 1) * 8 + lr) * XLD + (la >> 1) * 8) * 2);
    const uint32_t b_off = (uint32_t)((((la >> 1) * 8 + lr) * WLD + (la & 1) * 8) * 2);

    const uint32_t sb    = (uint32_t)__cvta_generic_to_shared(qsm);
    const uint32_t xhi_s = sb + (uint32_t)(wm * XLD * 2) + a_off;
    const uint32_t xlo_s = xhi_s + X_ARR;

    float acc[2][6][4];
    #pragma unroll
    for (int mi = 0; mi < 2; mi++)
        #pragma unroll
        for (int ni = 0; ni < 6; ni++)
            #pragma unroll
            for (int e = 0; e < 4; e++) acc[mi][ni][e] = 0.f;

    const int xr = tid >> 2;           // X row this thread stages (0..63)
    const int xq = (tid & 3) * 8;      // 8-float quarter

    // W staging: 768 16B-slots per array, 3 per thread
    auto stage_w = [&](uint32_t wbase, int k0) {
        #pragma unroll
        for (int i = 0; i < 3; i++) {
            const int s   = i * 256 + tid;
            const int row = s >> 2;
            const int seg = (s & 3) * 8;
            const size_t gof = (size_t)row * DD + k0 + seg;
            const uint32_t sdst = wbase + (uint32_t)((row * WLD + seg) * 2);
            CP_ASYNC16(sdst,         g_Whi + gof);
            CP_ASYNC16(sdst + W_ARR, g_Wlo + gof);
        }
    };

    // X register prefetch for tile 0 (8 floats = 2 float4 per thread)
    float4 xv[2];
    {
        const float4* src = (const float4*)(x + (size_t)(m0 + xr) * DD + 0 + xq);
        xv[0] = src[0];
        xv[1] = src[1];
    }
    stage_w(sb + (uint32_t)(2 * X_ARR), 0);
    CP_COMMIT();

    int wcur = 0;
    for (int k0 = 0; k0 < DD; k0 += GM_BK) {
        __syncthreads();   // X buffer free (previous tile's mma done)

        // store split X (current tile) to smem
        #pragma unroll
        for (int i = 0; i < 2; i++) {
            const int o = xr * XLD + xq + i * 4;
            uint32_t h0, l0, h1, l1;
            split2(xv[i].x, xv[i].y, h0, l0);
            split2(xv[i].z, xv[i].w, h1, l1);
            *(uint32_t*)(xhi + o + 0) = h0;
            *(uint32_t*)(xhi + o + 2) = h1;
            *(uint32_t*)(xlo + o + 0) = l0;
            *(uint32_t*)(xlo + o + 2) = l1;
        }

        if (k0 + GM_BK < DD) {
            const float4* src = (const float4*)(x + (size_t)(m0 + xr) * DD + (k0 + GM_BK) + xq);
            xv[0] = src[0];
            xv[1] = src[1];
            stage_w(sb + (uint32_t)(2 * X_ARR + (wcur ^ 1) * WBUF), k0 + GM_BK);
            CP_COMMIT();
            CP_WAIT1();    // current W tile complete; next may stay in flight
        } else {
            CP_WAIT0();
        }
        __syncthreads();

        const uint32_t wbase = sb + (uint32_t)(2 * X_ARR + wcur * WBUF)
                             + (uint32_t)(wn * WLD * 2) + b_off;

        #pragma unroll
        for (int kk = 0; kk < GM_BK; kk += 16) {
            const uint32_t ko = (uint32_t)(kk * 2);
            uint32_t ah[4], al[4];
            ldsm4(ah, xhi_s + ko);        // both 16-row groups via x4? no: one ldsm4 = rows wm..wm+15 only
            // A warp tile is 32 rows = two 16-row fragments:
            uint32_t ah2[4], al2[4];
            ldsm4(ah2, xhi_s + (uint32_t)(16 * XLD * 2) + ko);
            ldsm4(al,  xlo_s + ko);
            ldsm4(al2, xlo_s + (uint32_t)(16 * XLD * 2) + ko);

            #pragma unroll
            for (int nj = 0; nj < 3; nj++) {
                uint32_t bh[4], bl[4];
                const uint32_t woff = (uint32_t)(nj * (16 * WLD * 2)) + ko;
                ldsm4(bh, wbase + woff);
                ldsm4(bl, wbase + woff + W_ARR);
                // mi = 0 (rows wm..wm+15)
                mma16816(acc[0][2*nj],   ah, bh);
                mma16816(acc[0][2*nj+1], ah, bh + 2);
                mma16816(acc[0][2*nj],   ah, bl);
                mma16816(acc[0][2*nj+1], ah, bl + 2);
                mma16816(acc[0][2*nj],   al, bh);
                mma16816(acc[0][2*nj+1], al, bh + 2);
                // mi = 1 (rows wm+16..wm+31)
                mma16816(acc[1][2*nj],   ah2, bh);
                mma16816(acc[1][2*nj+1], ah2, bh + 2);
                mma16816(acc[1][2*nj],   ah2, bl);
                mma16816(acc[1][2*nj+1], ah2, bl + 2);
                mma16816(acc[1][2*nj],   al2, bh);
                mma16816(acc[1][2*nj+1], al2, bh + 2);
            }
        }
        wcur ^= 1;
    }

    // ---- epilogue: split to bf16 hi/lo, route to Q/K/V by column ----
    #pragma unroll
    for (int mi = 0; mi < 2; mi++) {
        #pragma unroll
        for (int ni = 0; ni < 6; ni++) {
            const size_t r0 = (size_t)m0 + wm + mi * 16 + g;
            const int    c  = wn + ni * 8 + 2 * t4;
            const int    nb = c >> 6;       // 0=Q 1=K 2=V
            const int    ci = c & 63;
            __nv_bfloat16* dhi = (nb == 0) ? g_Qhi : (nb == 1) ? g_Khi : g_Vhi;
            __nv_bfloat16* dlo = (nb == 0) ? g_Qlo : (nb == 1) ? g_Klo : g_Vlo;
            uint32_t h, l;
            split2(acc[mi][ni][0], acc[mi][ni][1], h, l);
            *(uint32_t*)(dhi + r0 * HD + ci) = h;
            *(uint32_t*)(dlo + r0 * HD + ci) = l;
            split2(acc[mi][ni][2], acc[mi][ni][3], h, l);
            *(uint32_t*)(dhi + (r0 + 8) * HD + ci) = h;
            *(uint32_t*)(dlo + (r0 + 8) * HD + ci) = l;
        }
    }
}

// ---------------------------------------------------------------------------
// Kernel 2: split-K causal flash attention, cp.async double-buffered. CK=512.
// (Unchanged from R14 champion: no min-blocks, heavy tiles first.)
// ---------------------------------------------------------------------------
#define TLD 72
#define ARR_B  (64 * TLD * 2)
#define BUF_B  (4 * ARR_B)
#define ATTN_SMEM (2 * BUF_B)

__global__ __launch_bounds__(128) void attn_mma()
{
    extern __shared__ char dsm[];

    const int chunk = blockIdx.x;
    const int tile  = (TILES - 1) - blockIdx.y;   // heavy tiles launch first
    const int b     = blockIdx.z;

    const int kmax = (tile + 1) * QT;
    const int nch  = (kmax + CK - 1) / CK;
    if (chunk >= nch) return;

    const int kstart = chunk * CK;
    const int kend   = min(kstart + CK, kmax);
    const int q0     = tile * QT;

    const int tid  = threadIdx.x;
    const int warp = tid >> 5;
    const int lane = tid & 31;
    const int g    = lane >> 2;
    const int t4   = lane & 3;

    const size_t boff = (size_t)b * TT_SEQ * HD;
    const uint32_t sb = (uint32_t)__cvta_generic_to_shared(dsm);

    const int la = lane >> 3;
    const int lr = lane & 7;
    const uint32_t k_lane_off = (uint32_t)((((la >> 1) * 8 + lr) * TLD + (la & 1) * 8) * 2);
    const uint32_t v_lane_off = (uint32_t)((((la & 1) * 8 + lr) * TLD + (la >> 1) * 8) * 2);

    uint32_t Qh[2][4][4], Ql[2][4][4];
    #pragma unroll
    for (int mi = 0; mi < 2; mi++) {
        const size_t ar = boff + (size_t)(q0 + warp * 32 + mi * 16 + g) * HD;
        #pragma unroll
        for (int ks = 0; ks < 4; ks++) {
            const int c = ks * 16 + 2 * t4;
            Qh[mi][ks][0] = *(const uint32_t*)(g_Qhi + ar + c);
            Qh[mi][ks][1] = *(const uint32_t*)(g_Qhi + ar + 8 * HD + c);
            Qh[mi][ks][2] = *(const uint32_t*)(g_Qhi + ar + c + 8);
            Qh[mi][ks][3] = *(const uint32_t*)(g_Qhi + ar + 8 * HD + c + 8);
            Ql[mi][ks][0] = *(const uint32_t*)(g_Qlo + ar + c);
            Ql[mi][ks][1] = *(const uint32_t*)(g_Qlo + ar + 8 * HD + c);
            Ql[mi][ks][2] = *(const uint32_t*)(g_Qlo + ar + c + 8);
            Ql[mi][ks][3] = *(const uint32_t*)(g_Qlo + ar + 8 * HD + c + 8);
        }
    }

    float o[2][8][4];
    #pragma unroll
    for (int mi = 0; mi < 2; mi++)
        #pragma unroll
        for (int ni = 0; ni < 8; ni++)
            #pragma unroll
            for (int e = 0; e < 4; e++) o[mi][ni][e] = 0.f;
    float m_[2][2] = {{-1e20f, -1e20f}, {-1e20f, -1e20f}};
    float l_[2][2] = {{0.f, 0.f}, {0.f, 0.f}};

    auto stage_tile = [&](uint32_t sbase, int k0) {
        #pragma unroll
        for (int i = 0; i < 4; i++) {
            const int idx = i * 128 + tid;
            const int row = idx >> 3;
            const int seg = (idx & 7) * 8;
            const size_t gsrc = boff + (size_t)(k0 + row) * HD + seg;
            const uint32_t sdst = sbase + (uint32_t)((row * TLD + seg) * 2);
            CP_ASYNC16(sdst + 0 * ARR_B, g_Khi + gsrc);
            CP_ASYNC16(sdst + 1 * ARR_B, g_Klo + gsrc);
            CP_ASYNC16(sdst + 2 * ARR_B, g_Vhi + gsrc);
            CP_ASYNC16(sdst + 3 * ARR_B, g_Vlo + gsrc);
        }
    };

    stage_tile(sb, kstart);
    CP_COMMIT();

    int cur = 0;
    for (int k0 = kstart; k0 < kend; k0 += 64) {
        CP_WAIT0();
        __syncthreads();
        if (k0 + 64 < kend) {
            stage_tile(sb + (uint32_t)((cur ^ 1) * BUF_B), k0 + 64);
            CP_COMMIT();
        }

        const uint32_t bufb  = sb + (uint32_t)(cur * BUF_B);
        const uint32_t khi_s = bufb + 0 * ARR_B + k_lane_off;
        const uint32_t klo_s = bufb + 1 * ARR_B + k_lane_off;
        const uint32_t vhi_s = bufb + 2 * ARR_B + v_lane_off;
        const uint32_t vlo_s = bufb + 3 * ARR_B + v_lane_off;

        #pragma unroll
        for (int mi = 0; mi < 2; mi++) {
            const int rbase = warp * 32 + mi * 16;

            float s[8][4];
            #pragma unroll
            for (int ni = 0; ni < 8; ni++)
                #pragma unroll
                for (int e = 0; e < 4; e++) s[ni][e] = 0.f;

            #pragma unroll
            for (int ks = 0; ks < 4; ks++) {
                #pragma unroll
                for (int p = 0; p < 4; p++) {
                    const uint32_t off = (uint32_t)(p * (16 * TLD * 2) + ks * 32);
                    uint32_t bh[4], bl[4];
                    ldsm4(bh, khi_s + off);
                    ldsm4(bl, klo_s + off);
                    mma16816(s[2*p],   Qh[mi][ks], bh);
                    mma16816(s[2*p],   Qh[mi][ks], bl);
                    mma16816(s[2*p],   Ql[mi][ks], bh);
                    mma16816(s[2*p+1], Qh[mi][ks], bh + 2);
                    mma16816(s[2*p+1], Qh[mi][ks], bl + 2);
                    mma16816(s[2*p+1], Ql[mi][ks], bh + 2);
                }
            }

            if (k0 + 63 > q0 + rbase) {
                const int qa = q0 + rbase + g;
                #pragma unroll
                for (int ni = 0; ni < 8; ni++) {
                    const int kc = k0 + ni * 8 + 2 * t4;
                    if (kc     > qa)     s[ni][0] = -1e30f;
                    if (kc + 1 > qa)     s[ni][1] = -1e30f;
                    if (kc     > qa + 8) s[ni][2] = -1e30f;
                    if (kc + 1 > qa + 8) s[ni][3] = -1e30f;
                }
            }

            float mxA = -1e30f, mxB = -1e30f;
            #pragma unroll
            for (int ni = 0; ni < 8; ni++) {
                mxA = fmaxf(mxA, fmaxf(s[ni][0], s[ni][1]));
                mxB = fmaxf(mxB, fmaxf(s[ni][2], s[ni][3]));
            }
            mxA = fmaxf(mxA, __shfl_xor_sync(0xffffffffu, mxA, 1));
            mxA = fmaxf(mxA, __shfl_xor_sync(0xffffffffu, mxA, 2));
            mxB = fmaxf(mxB, __shfl_xor_sync(0xffffffffu, mxB, 1));
            mxB = fmaxf(mxB, __shfl_xor_sync(0xffffffffu, mxB, 2));

            const float mA = fmaxf(m_[mi][0], mxA);
            const float mB = fmaxf(m_[mi][1], mxB);
            const float scA = __expf(m_[mi][0] - mA);
            const float scB = __expf(m_[mi][1] - mB);
            m_[mi][0] = mA; m_[mi][1] = mB;

            uint32_t Ph[4][4], Pl[4][4];
            float sA = 0.f, sB = 0.f;
            #pragma unroll
            for (int ni = 0; ni < 8; ni++) {
                float p0 = __expf(s[ni][0] - mA);
                float p1 = __expf(s[ni][1] - mA);
                float p2 = __expf(s[ni][2] - mB);
                float p3 = __expf(s[ni][3] - mB);
                sA += p0 + p1; sB += p2 + p3;
                const int ks   = ni >> 1;
                const int base = (ni & 1) * 2;
                split2(p0, p1, Ph[ks][base + 0], Pl[ks][base + 0]);
                split2(p2, p3, Ph[ks][base + 1], Pl[ks][base + 1]);
            }
            sA += __shfl_xor_sync(0xffffffffu, sA, 1);
            sA += __shfl_xor_sync(0xffffffffu, sA, 2);
            sB += __shfl_xor_sync(0xffffffffu, sB, 1);
            sB += __shfl_xor_sync(0xffffffffu, sB, 2);
            l_[mi][0] = l_[mi][0] * scA + sA;
            l_[mi][1] = l_[mi][1] * scB + sB;

            #pragma unroll
            for (int ni = 0; ni < 8; ni++) {
                o[mi][ni][0] *= scA; o[mi][ni][1] *= scA;
                o[mi][ni][2] *= scB; o[mi][ni][3] *= scB;
            }

            #pragma unroll
            for (int ks = 0; ks < 4; ks++) {
                #pragma unroll
                for (int p = 0; p < 4; p++) {
                    const uint32_t off = (uint32_t)(ks * (16 * TLD * 2) + p * 32);
                    uint32_t bh[4], bl[4];
                    ldsm4t(bh, vhi_s + off);
                    ldsm4t(bl, vlo_s + off);
                    mma16816(o[mi][2*p],   Ph[ks], bh);
                    mma16816(o[mi][2*p],   Ph[ks], bl);
                    mma16816(o[mi][2*p],   Pl[ks], bh);
                    mma16816(o[mi][2*p+1], Ph[ks], bh + 2);
                    mma16816(o[mi][2*p+1], Ph[ks], bl + 2);
                    mma16816(o[mi][2*p+1], Pl[ks], bh + 2);
                }
            }
        }
        __syncthreads();
        cur ^= 1;
    }

    const size_t pbase = ((size_t)(b * TILES + tile) * NCH_MAX + chunk) * QT;
    #pragma unroll
    for (int mi = 0; mi < 2; mi++) {
        const int lrA = warp * 32 + mi * 16 + g;
        if (t4 == 0) {
            g_pm[pbase + lrA]     = m_[mi][0];
            g_pl[pbase + lrA]     = l_[mi][0];
            g_pm[pbase + lrA + 8] = m_[mi][1];
            g_pl[pbase + lrA + 8] = l_[mi][1];
        }
        #pragma unroll
        for (int ni = 0; ni < 8; ni++) {
            const int c = ni * 8 + 2 * t4;
            float2 vA, vB;
            vA.x = o[mi][ni][0]; vA.y = o[mi][ni][1];
            vB.x = o[mi][ni][2]; vB.y = o[mi][ni][3];
            *(float2*)(g_pacc + (pbase + lrA) * HD + c)       = vA;
            *(float2*)(g_pacc + (pbase + lrA + 8) * HD + c)   = vB;
        }
    }
}

// ---------------------------------------------------------------------------
// Kernel 3: combine split-K partials, float4 vectorized.
// ---------------------------------------------------------------------------
__global__ __launch_bounds__(256) void combine_kernel(float* __restrict__ out)
{
    const int gid = blockIdx.x * 256 + threadIdx.x;
    const int q   = gid >> 4;
    const int d   = (gid & 15) * 4;

    const int b      = q / TT_SEQ;
    const int t_in_b = q % TT_SEQ;
    const int tile   = t_in_b / QT;
    const int qi     = t_in_b % QT;

    const int kmax = (tile + 1) * QT;
    const int nch  = (kmax + CK - 1) / CK;

    const size_t base = ((size_t)(b * TILES + tile) * NCH_MAX) * QT + qi;

    float mstar = -1e30f;
    for (int i = 0; i < nch; i++) {
        float mi = g_pm[base + (size_t)i * QT];
        mstar = fmaxf(mstar, mi);
    }

    float L = 0.f;
    float4 val = make_float4(0.f, 0.f, 0.f, 0.f);
    for (int i = 0; i < nch; i++) {
        const size_t pidx = base + (size_t)i * QT;
        float w = __expf(g_pm[pidx] - mstar);
        L += g_pl[pidx] * w;
        float4 a = *(const float4*)(g_pacc + pidx * HD + d);
        val.x += a.x * w; val.y += a.y * w;
        val.z += a.z * w; val.w += a.w * w;
    }

    const float inv = 1.f / L;
    float4 r;
    r.x = val.x * inv; r.y = val.y * inv; r.z = val.z * inv; r.w = val.w * inv;
    *(float4*)(out + (size_t)q * HD + d) = r;
}

extern "C" void kernel_launch(void* const* d_in, const int* in_sizes, int n_in,
                              void* d_out, int out_size)
{
    const float* x  = (const float*)d_in[0];
    const float* Wq = (const float*)d_in[1];
    const float* Wk = (const float*)d_in[2];
    const float* Wv = (const float*)d_in[3];
    float* out = (float*)d_out;

    cudaFuncSetAttribute(qkv_fused, cudaFuncAttributeMaxDynamicSharedMemorySize, QKV_SMEM);
    cudaFuncSetAttribute(attn_mma, cudaFuncAttributeMaxDynamicSharedMemorySize, ATTN_SMEM);

    convert_w<<<(3 * HD * DD / 4) / 256, 256>>>(Wq, Wk, Wv);

    qkv_fused<<<NTOK / GM_BM, 256, QKV_SMEM>>>(x);

    dim3 agrid(NCH_MAX, TILES, BB);
    attn_mma<<<agrid, 128, ATTN_SMEM>>>();

    combine_kernel<<<(NTOK * 16) / 256, 256>>>(out);
}